// round 1
// baseline (speedup 1.0000x reference)
#include <cuda_runtime.h>
#include <math.h>

// Problem constants (fixed shapes from reference)
constexpr int BB = 4096;   // batch
constexpr int DD = 1024;   // ev_context dim
constexpr int HH = 1024;   // hidden
constexpr int TT = 50;     // timesteps
constexpr int H3 = 3 * HH; // 3 gates

// Scratch: ping-pong hidden state (2 x 16 MB) + gate preactivations (48 MB)
__device__ float g_h[2][(size_t)BB * HH];
__device__ float g_gh[(size_t)BB * H3];

__device__ __forceinline__ float sigmoidf_(float x) {
    return 1.0f / (1.0f + __expf(-x));
}
__device__ __forceinline__ float tanh_fast(float x) {
    // tanh(x) = 2*sigmoid(2x) - 1 ; __expf is ~2 ulp accurate -> abs err ~1e-7
    return 2.0f / (1.0f + __expf(-2.0f * x)) - 1.0f;
}

// ----------------------------------------------------------------------------
// GEMM: C(MxN) = A(MxK) * Bm(NxK)^T  (all row-major)
// BM=BN=128, BK=8, 256 threads, 8x8 per thread.
// EPI == 0: C = acc              (raw gate preactivations)
// EPI == 1: C = tanh(acc + bias) (h0 path)
// M,N assumed multiples of 128; K multiple of 8 (true for all uses here).
// ----------------------------------------------------------------------------
template <int EPI>
__global__ __launch_bounds__(256, 2) void gemm_kernel(
    const float* __restrict__ A, const float* __restrict__ Bm,
    float* __restrict__ C, int M, int N, int K,
    const float* __restrict__ bias)
{
    __shared__ __align__(16) float As[8][128];
    __shared__ __align__(16) float Bs[8][128];

    const int tid = threadIdx.x;
    const int bm = blockIdx.y;
    const int bn = blockIdx.x;

    const float* Ablk = A + (size_t)bm * 128 * K;
    const float* Bblk = Bm + (size_t)bn * 128 * K;

    const int lr = tid >> 1;         // 0..127 tile row for loads
    const int lc = (tid & 1) * 4;    // 0 or 4 (k offset within BK)
    const int tx = tid & 15;         // N micro-tile index
    const int ty = tid >> 4;         // M micro-tile index

    float acc[8][8];
#pragma unroll
    for (int i = 0; i < 8; i++)
#pragma unroll
        for (int j = 0; j < 8; j++) acc[i][j] = 0.0f;

    for (int k0 = 0; k0 < K; k0 += 8) {
        float4 a4 = *(const float4*)(Ablk + (size_t)lr * K + k0 + lc);
        float4 b4 = *(const float4*)(Bblk + (size_t)lr * K + k0 + lc);
        As[lc + 0][lr] = a4.x; As[lc + 1][lr] = a4.y;
        As[lc + 2][lr] = a4.z; As[lc + 3][lr] = a4.w;
        Bs[lc + 0][lr] = b4.x; Bs[lc + 1][lr] = b4.y;
        Bs[lc + 2][lr] = b4.z; Bs[lc + 3][lr] = b4.w;
        __syncthreads();

#pragma unroll
        for (int k = 0; k < 8; k++) {
            float ra[8], rb[8];
            *(float4*)(ra)     = *(const float4*)&As[k][ty * 8];
            *(float4*)(ra + 4) = *(const float4*)&As[k][ty * 8 + 4];
            *(float4*)(rb)     = *(const float4*)&Bs[k][tx * 8];
            *(float4*)(rb + 4) = *(const float4*)&Bs[k][tx * 8 + 4];
#pragma unroll
            for (int i = 0; i < 8; i++)
#pragma unroll
                for (int j = 0; j < 8; j++)
                    acc[i][j] += ra[i] * rb[j];
        }
        __syncthreads();
    }

    const int row0 = bm * 128 + ty * 8;
    const int col0 = bn * 128 + tx * 8;
#pragma unroll
    for (int i = 0; i < 8; i++) {
        float* crow = C + (size_t)(row0 + i) * N + col0;
#pragma unroll
        for (int j = 0; j < 8; j++) {
            float v = acc[i][j];
            if (EPI == 1) v = tanh_fast(v + bias[col0 + j]);
            crow[j] = v;
        }
    }
}

// ----------------------------------------------------------------------------
// GRU gate update: reads raw gh = h @ w_hh^T, computes gx inline (input dim 2),
// applies PyTorch GRU cell (r,z,n order), writes h_new.
// prev_t = teacher_deltas[:, t-1] (zeros at t=0) since free_running_ratio = 0.
// ----------------------------------------------------------------------------
__global__ void gate_kernel(
    const float* __restrict__ gh, const float* __restrict__ hprev,
    float* __restrict__ hnew, const float* __restrict__ teacher, int t,
    const float* __restrict__ w_ih, const float* __restrict__ b_ih,
    const float* __restrict__ b_hh)
{
    int idx = blockIdx.x * blockDim.x + threadIdx.x;
    if (idx >= BB * HH) return;
    int b = idx >> 10;       // H == 1024
    int i = idx & (HH - 1);

    float p0 = 0.0f, p1 = 0.0f;
    if (t > 0) {
        size_t to = ((size_t)b * TT + (t - 1)) * 2;
        p0 = teacher[to];
        p1 = teacher[to + 1];
    }

    const float* ghrow = gh + (size_t)b * H3;
    float hr = ghrow[i]          + b_hh[i];
    float hz = ghrow[HH + i]     + b_hh[HH + i];
    float hn = ghrow[2 * HH + i] + b_hh[2 * HH + i];

    float xr = w_ih[2 * i]              * p0 + w_ih[2 * i + 1]              * p1 + b_ih[i];
    float xz = w_ih[2 * (HH + i)]       * p0 + w_ih[2 * (HH + i) + 1]       * p1 + b_ih[HH + i];
    float xn = w_ih[2 * (2 * HH + i)]   * p0 + w_ih[2 * (2 * HH + i) + 1]   * p1 + b_ih[2 * HH + i];

    float r = sigmoidf_(xr + hr);
    float z = sigmoidf_(xz + hz);
    float n = tanh_fast(xn + r * hn);
    float h = hprev[idx];
    hnew[idx] = (1.0f - z) * n + z * h;
}

// ----------------------------------------------------------------------------
// delta = h_new @ w_out^T + b_out : one block per batch row, reduce over H.
// Writes pred_deltas[b, t, :] directly into d_out.
// ----------------------------------------------------------------------------
__global__ void delta_kernel(
    const float* __restrict__ h, const float* __restrict__ w_out,
    const float* __restrict__ b_out, float* __restrict__ deltas, int t)
{
    int b = blockIdx.x;
    const float* hrow = h + (size_t)b * HH;
    float s0 = 0.0f, s1 = 0.0f;
    for (int i = threadIdx.x; i < HH; i += 256) {
        float hv = hrow[i];
        s0 += hv * w_out[i];
        s1 += hv * w_out[HH + i];
    }
#pragma unroll
    for (int o = 16; o > 0; o >>= 1) {
        s0 += __shfl_xor_sync(0xFFFFFFFFu, s0, o);
        s1 += __shfl_xor_sync(0xFFFFFFFFu, s1, o);
    }
    __shared__ float sm0[8], sm1[8];
    int w = threadIdx.x >> 5;
    if ((threadIdx.x & 31) == 0) { sm0[w] = s0; sm1[w] = s1; }
    __syncthreads();
    if (threadIdx.x == 0) {
        float a0 = 0.0f, a1 = 0.0f;
#pragma unroll
        for (int i = 0; i < 8; i++) { a0 += sm0[i]; a1 += sm1[i]; }
        size_t o = ((size_t)b * TT + t) * 2;
        deltas[o]     = a0 + b_out[0];
        deltas[o + 1] = a1 + b_out[1];
    }
}

// pred_pos = cumsum(pred_deltas, axis=T) : one thread per (b, channel)
__global__ void cumsum_kernel(const float* __restrict__ deltas, float* __restrict__ pos)
{
    int idx = blockIdx.x * blockDim.x + threadIdx.x;
    if (idx >= BB * 2) return;
    int b = idx >> 1, c = idx & 1;
    float acc = 0.0f;
    for (int t = 0; t < TT; t++) {
        size_t o = ((size_t)b * TT + t) * 2 + c;
        acc += deltas[o];
        pos[o] = acc;
    }
}

// ----------------------------------------------------------------------------
// kernel_launch: graph-capturable, allocation-free.
// Inputs (metadata order): ev_context, teacher_deltas, w_init, b_init,
//                          w_ih, w_hh, b_ih, b_hh, w_out, b_out
// Output: [pred_deltas (B,T,2) | pred_pos (B,T,2)] flattened fp32.
// ----------------------------------------------------------------------------
extern "C" void kernel_launch(void* const* d_in, const int* in_sizes, int n_in,
                              void* d_out, int out_size)
{
    const float* ev     = (const float*)d_in[0];
    const float* teach  = (const float*)d_in[1];
    const float* w_init = (const float*)d_in[2];
    const float* b_init = (const float*)d_in[3];
    const float* w_ih   = (const float*)d_in[4];
    const float* w_hh   = (const float*)d_in[5];
    const float* b_ih   = (const float*)d_in[6];
    const float* b_hh   = (const float*)d_in[7];
    const float* w_out  = (const float*)d_in[8];
    const float* b_out  = (const float*)d_in[9];
    float* out = (float*)d_out;

    float* hbase = nullptr;
    float* ghbuf = nullptr;
    cudaGetSymbolAddress((void**)&hbase, g_h);
    cudaGetSymbolAddress((void**)&ghbuf, g_gh);
    float* hbuf[2] = { hbase, hbase + (size_t)BB * HH };

    dim3 blk(256);

    // h0 = tanh(ev @ w_init^T + b_init)
    gemm_kernel<1><<<dim3(HH / 128, BB / 128), blk>>>(
        ev, w_init, hbuf[0], BB, HH, DD, b_init);

    for (int t = 0; t < TT; t++) {
        int cur = t & 1;
        int nxt = cur ^ 1;
        // gh = h @ w_hh^T  (raw, biases added in gate kernel)
        gemm_kernel<0><<<dim3(H3 / 128, BB / 128), blk>>>(
            hbuf[cur], w_hh, ghbuf, BB, H3, HH, nullptr);
        // gates + h_new
        gate_kernel<<<(BB * HH) / 256, 256>>>(
            ghbuf, hbuf[cur], hbuf[nxt], teach, t, w_ih, b_ih, b_hh);
        // delta projection -> pred_deltas
        delta_kernel<<<BB, 256>>>(hbuf[nxt], w_out, b_out, out, t);
    }

    // pred_pos = cumsum(pred_deltas)
    if (out_size >= 2 * BB * TT * 2) {
        cumsum_kernel<<<(BB * 2 + 255) / 256, 256>>>(out, out + (size_t)BB * TT * 2);
    }
}

// round 4
// speedup vs baseline: 2.1303x; 2.1303x over previous
#include <cuda_runtime.h>
#include <cuda_bf16.h>
#include <stdint.h>

// ---------------------------------------------------------------------------
// Problem constants
// ---------------------------------------------------------------------------
constexpr int BB = 4096;   // batch
constexpr int DD = 1024;   // ev_context dim
constexpr int HH = 1024;   // hidden
constexpr int TT = 50;     // timesteps

// ---------------------------------------------------------------------------
// Device scratch (no allocs): ping-pong h (fp32 + bf16 hi/lo), split weights
// ---------------------------------------------------------------------------
__device__ float         g_h  [2][(size_t)BB * HH];
__device__ __nv_bfloat16 g_hhi[2][(size_t)BB * HH];
__device__ __nv_bfloat16 g_hlo[2][(size_t)BB * HH];
__device__ __nv_bfloat16 g_whi[(size_t)3 * HH * HH];
__device__ __nv_bfloat16 g_wlo[(size_t)3 * HH * HH];

__device__ __forceinline__ float sigmoidf_(float x) {
    return 1.0f / (1.0f + __expf(-x));
}
__device__ __forceinline__ float tanh_fast(float x) {
    return 2.0f / (1.0f + __expf(-2.0f * x)) - 1.0f;
}

// ---------------------------------------------------------------------------
// PTX helpers: portable sm_80+ instructions only (compute_103-safe).
// ---------------------------------------------------------------------------
__device__ __forceinline__ uint32_t smem_u32(const void* p) {
    uint32_t a;
    asm("{ .reg .u64 t; cvta.to.shared.u64 t, %1; cvt.u32.u64 %0, t; }"
        : "=r"(a) : "l"(p));
    return a;
}
__device__ __forceinline__ uint32_t swz(uint32_t o) {   // SW128: 16B-granular XOR
    return o ^ ((o >> 3) & 0x70);
}
__device__ __forceinline__ void cp_async16(uint32_t dst, const void* src) {
    asm volatile("cp.async.cg.shared.global [%0], [%1], 16;"
                 :: "r"(dst), "l"(src) : "memory");
}
__device__ __forceinline__ void cp_commit() {
    asm volatile("cp.async.commit_group;" ::: "memory");
}
__device__ __forceinline__ void cp_wait1() {
    asm volatile("cp.async.wait_group 1;" ::: "memory");
}
__device__ __forceinline__ void ldsm4(uint32_t* r, uint32_t a) {
    asm volatile("ldmatrix.sync.aligned.m8n8.x4.shared.b16 {%0,%1,%2,%3}, [%4];"
                 : "=r"(r[0]), "=r"(r[1]), "=r"(r[2]), "=r"(r[3]) : "r"(a));
}
__device__ __forceinline__ void mma16816(float* d, const uint32_t* a, const uint32_t* b) {
    asm volatile(
        "mma.sync.aligned.m16n8k16.row.col.f32.bf16.bf16.f32 "
        "{%0,%1,%2,%3}, {%4,%5,%6,%7}, {%8,%9}, {%0,%1,%2,%3};"
        : "+f"(d[0]), "+f"(d[1]), "+f"(d[2]), "+f"(d[3])
        : "r"(a[0]), "r"(a[1]), "r"(a[2]), "r"(a[3]), "r"(b[0]), "r"(b[1]));
}

// Stage: A tile 128x64 bf16 (16KB) + B tile 192x64 bf16 (24KB), double-buffered
constexpr int STAGE  = 40960;
constexpr int OFF_B  = 16384;
constexpr int NCHUNK = 48;                 // 3 segments x 16 chunks of K=64
constexpr int PITCH  = 196;                // epilogue gh smem pitch (floats)
constexpr int SMEM_BYTES = 128 * PITCH * 4; // 100352 > 2*STAGE (81920)

// issue cp.async loads for chunk c into stage s
__device__ __forceinline__ void load_chunk(
    int c, int s, int tid, int bm, int bu, uint32_t sbase,
    const __nv_bfloat16* hhi, const __nv_bfloat16* hlo,
    const __nv_bfloat16* whi, const __nv_bfloat16* wlo)
{
    const int seg = c >> 4;
    const int kk = (c & 15) * 64;
    const __nv_bfloat16* sa = (seg < 2) ? hhi : hlo;
    const __nv_bfloat16* sb = (seg == 1) ? wlo : whi;
    const uint32_t stA = sbase + s * STAGE;
    const uint32_t stB = stA + OFF_B;

    // A: 128 rows x 64 k -> 1024 x 16B
#pragma unroll
    for (int i = 0; i < 3; i++) {
        int v = tid + i * 384;
        if (v < 1024) {
            int r = v >> 3, kv = v & 7;
            cp_async16(stA + swz(r * 128 + kv * 16),
                       sa + (size_t)(bm * 128 + r) * 1024 + kk + kv * 8);
        }
    }
    // B: 192 rows (3 gates x 64 units) x 64 k -> 1536 x 16B
#pragma unroll
    for (int i = 0; i < 4; i++) {
        int v = tid + i * 384;
        int j = v >> 3, kv = v & 7;
        int g = j >> 6, u = j & 63;
        cp_async16(stB + swz(j * 128 + kv * 16),
                   sb + (size_t)(g * 1024 + bu * 64 + u) * 1024 + kk + kv * 8);
    }
}

// ---------------------------------------------------------------------------
// Fused recurrent step (HMMA): tile 128 batch x (3 gates x 64 units)
// grid (16, 32), 384 threads, dyn smem SMEM_BYTES
// ---------------------------------------------------------------------------
__global__ __launch_bounds__(384, 1) void gru_step_kernel(
    const float* __restrict__ hprev,
    const __nv_bfloat16* __restrict__ hhi, const __nv_bfloat16* __restrict__ hlo,
    float* __restrict__ hout,
    __nv_bfloat16* __restrict__ hhio, __nv_bfloat16* __restrict__ hloo,
    const __nv_bfloat16* __restrict__ whi, const __nv_bfloat16* __restrict__ wlo,
    const float* __restrict__ teacher, int t,
    const float* __restrict__ b_hh, const float* __restrict__ w_ih,
    const float* __restrict__ b_ih, const float* __restrict__ w_out,
    float* __restrict__ deltas)
{
    extern __shared__ __align__(1024) char smem[];
    const uint32_t sbase = smem_u32(smem);
    const int tid = threadIdx.x;
    const int lane = tid & 31, wid = tid >> 5;
    const int bu = blockIdx.x, bm = blockIdx.y;
    const int wm = wid & 3, wg = wid >> 2;   // warp grid 4(m) x 3(gate)
    const int m0 = wm * 32;

    float acc[2][8][4];
#pragma unroll
    for (int a = 0; a < 2; a++)
#pragma unroll
        for (int b = 0; b < 8; b++)
#pragma unroll
            for (int q = 0; q < 4; q++) acc[a][b][q] = 0.0f;

    load_chunk(0, 0, tid, bm, bu, sbase, hhi, hlo, whi, wlo);
    cp_commit();

    for (int c = 0; c < NCHUNK; c++) {
        const int s = c & 1;
        if (c + 1 < NCHUNK)
            load_chunk(c + 1, s ^ 1, tid, bm, bu, sbase, hhi, hlo, whi, wlo);
        cp_commit();
        cp_wait1();
        __syncthreads();

        const uint32_t stA = sbase + s * STAGE;
        const uint32_t stB = stA + OFF_B;
#pragma unroll
        for (int ks = 0; ks < 4; ks++) {
            uint32_t af[2][4];
#pragma unroll
            for (int mt = 0; mt < 2; mt++) {
                int r = m0 + mt * 16 + (lane & 15);
                int kb = ks * 32 + ((lane >> 4) << 4);
                ldsm4(af[mt], stA + swz(r * 128 + kb));
            }
            uint32_t bf[4][4];
#pragma unroll
            for (int p = 0; p < 4; p++) {
                int r = wg * 64 + p * 16 + (lane & 7) + ((lane & 16) ? 8 : 0);
                int kb = ks * 32 + ((lane & 8) ? 16 : 0);
                ldsm4(bf[p], stB + swz(r * 128 + kb));
            }
#pragma unroll
            for (int mt = 0; mt < 2; mt++)
#pragma unroll
                for (int p = 0; p < 4; p++) {
                    mma16816(acc[mt][2 * p],     af[mt], &bf[p][0]);
                    mma16816(acc[mt][2 * p + 1], af[mt], &bf[p][2]);
                }
        }
        __syncthreads();
    }

    // ------ epilogue: accs -> smem gh tile (overlays stages; sync'd above) ---
    float* ghs = (float*)smem;
#pragma unroll
    for (int mt = 0; mt < 2; mt++)
#pragma unroll
        for (int nf = 0; nf < 8; nf++) {
            int row = m0 + mt * 16 + (lane >> 2);
            int col = wg * 64 + nf * 8 + 2 * (lane & 3);
            *(float2*)&ghs[row * PITCH + col] =
                make_float2(acc[mt][nf][0], acc[mt][nf][1]);
            *(float2*)&ghs[(row + 8) * PITCH + col] =
                make_float2(acc[mt][nf][2], acc[mt][nf][3]);
        }
    __syncthreads();

    // ------ GRU cell + delta partials: warps 0-7, lane = unit offset ---------
    if (tid < 256) {
        const int u = tid & 63;          // warp w: u in [32w%64, +32)
        const int r0 = tid >> 6;         // 4 row groups of 32
        const int col = bu * 64 + u;

        const float bhr = b_hh[col], bhz = b_hh[HH + col], bhn = b_hh[2 * HH + col];
        const float wr0 = w_ih[2 * col],            wr1 = w_ih[2 * col + 1];
        const float wz0 = w_ih[2 * (HH + col)],     wz1 = w_ih[2 * (HH + col) + 1];
        const float wn0 = w_ih[2 * (2 * HH + col)], wn1 = w_ih[2 * (2 * HH + col) + 1];
        const float bir = b_ih[col], biz = b_ih[HH + col], bin_ = b_ih[2 * HH + col];
        const float wo0 = w_out[col], wo1 = w_out[HH + col];

        for (int k = 0; k < 32; k++) {
            const int r = r0 * 32 + k;
            const int rg = bm * 128 + r;
            float p0 = 0.0f, p1 = 0.0f;
            if (t > 0) {
                size_t to = ((size_t)rg * TT + (t - 1)) * 2;
                p0 = teacher[to]; p1 = teacher[to + 1];
            }
            float hr = ghs[r * PITCH + u]        + bhr;
            float hz = ghs[r * PITCH + 64 + u]   + bhz;
            float hn = ghs[r * PITCH + 128 + u]  + bhn;
            float rr = sigmoidf_(wr0 * p0 + wr1 * p1 + bir + hr);
            float zz = sigmoidf_(wz0 * p0 + wz1 * p1 + biz + hz);
            float nn = tanh_fast(wn0 * p0 + wn1 * p1 + bin_ + rr * hn);
            size_t go = (size_t)rg * HH + col;
            float h = hprev[go];
            float hv = (1.0f - zz) * nn + zz * h;

            hout[go] = hv;
            __nv_bfloat16 hb = __float2bfloat16(hv);
            hhio[go] = hb;
            hloo[go] = __float2bfloat16(hv - __bfloat162float(hb));

            float s0 = hv * wo0, s1 = hv * wo1;
#pragma unroll
            for (int o = 16; o > 0; o >>= 1) {
                s0 += __shfl_xor_sync(0xFFFFFFFFu, s0, o);
                s1 += __shfl_xor_sync(0xFFFFFFFFu, s1, o);
            }
            if (lane == 0) {
                atomicAdd(&deltas[((size_t)rg * TT + t) * 2],     s0);
                atomicAdd(&deltas[((size_t)rg * TT + t) * 2 + 1], s1);
            }
        }
    }
}

// ---------------------------------------------------------------------------
// fp32 SGEMM for h0 = tanh(ev @ w_init^T + b_init)  (one-time)
// ---------------------------------------------------------------------------
__global__ __launch_bounds__(256, 2) void gemm_h0_kernel(
    const float* __restrict__ A, const float* __restrict__ Bm,
    float* __restrict__ C, int M, int N, int K, const float* __restrict__ bias)
{
    __shared__ __align__(16) float As[8][128];
    __shared__ __align__(16) float Bs[8][128];
    const int tid = threadIdx.x;
    const int bm = blockIdx.y, bn = blockIdx.x;
    const float* Ablk = A + (size_t)bm * 128 * K;
    const float* Bblk = Bm + (size_t)bn * 128 * K;
    const int lr = tid >> 1, lc = (tid & 1) * 4;
    const int tx = tid & 15, ty = tid >> 4;
    float acc[8][8];
#pragma unroll
    for (int i = 0; i < 8; i++)
#pragma unroll
        for (int j = 0; j < 8; j++) acc[i][j] = 0.0f;
    for (int k0 = 0; k0 < K; k0 += 8) {
        float4 a4 = *(const float4*)(Ablk + (size_t)lr * K + k0 + lc);
        float4 b4 = *(const float4*)(Bblk + (size_t)lr * K + k0 + lc);
        As[lc + 0][lr] = a4.x; As[lc + 1][lr] = a4.y;
        As[lc + 2][lr] = a4.z; As[lc + 3][lr] = a4.w;
        Bs[lc + 0][lr] = b4.x; Bs[lc + 1][lr] = b4.y;
        Bs[lc + 2][lr] = b4.z; Bs[lc + 3][lr] = b4.w;
        __syncthreads();
#pragma unroll
        for (int k = 0; k < 8; k++) {
            float ra[8], rb[8];
            *(float4*)(ra)     = *(const float4*)&As[k][ty * 8];
            *(float4*)(ra + 4) = *(const float4*)&As[k][ty * 8 + 4];
            *(float4*)(rb)     = *(const float4*)&Bs[k][tx * 8];
            *(float4*)(rb + 4) = *(const float4*)&Bs[k][tx * 8 + 4];
#pragma unroll
            for (int i = 0; i < 8; i++)
#pragma unroll
                for (int j = 0; j < 8; j++) acc[i][j] += ra[i] * rb[j];
        }
        __syncthreads();
    }
    const int row0 = bm * 128 + ty * 8, col0 = bn * 128 + tx * 8;
#pragma unroll
    for (int i = 0; i < 8; i++) {
        float* crow = C + (size_t)(row0 + i) * N + col0;
#pragma unroll
        for (int j = 0; j < 8; j++)
            crow[j] = tanh_fast(acc[i][j] + bias[col0 + j]);
    }
}

// split fp32 -> bf16 hi + lo residual
__global__ void split_kernel(const float* __restrict__ src,
                             __nv_bfloat16* __restrict__ hi,
                             __nv_bfloat16* __restrict__ lo, int n)
{
    int i = blockIdx.x * 256 + threadIdx.x;
    if (i < n) {
        float v = src[i];
        __nv_bfloat16 h = __float2bfloat16(v);
        hi[i] = h;
        lo[i] = __float2bfloat16(v - __bfloat162float(h));
    }
}

// deltas[b,t,c] = b_out[c]  (atomicAdd partials land on top)
__global__ void init_deltas_kernel(float* __restrict__ deltas, const float* __restrict__ b_out)
{
    int i = blockIdx.x * 256 + threadIdx.x;
    if (i < BB * TT * 2) deltas[i] = b_out[i & 1];
}

__global__ void cumsum_kernel(const float* __restrict__ deltas, float* __restrict__ pos)
{
    int idx = blockIdx.x * blockDim.x + threadIdx.x;
    if (idx >= BB * 2) return;
    int b = idx >> 1, c = idx & 1;
    float acc = 0.0f;
    for (int t = 0; t < TT; t++) {
        size_t o = ((size_t)b * TT + t) * 2 + c;
        acc += deltas[o];
        pos[o] = acc;
    }
}

// ---------------------------------------------------------------------------
// kernel_launch (graph-capturable, allocation-free)
// ---------------------------------------------------------------------------
extern "C" void kernel_launch(void* const* d_in, const int* in_sizes, int n_in,
                              void* d_out, int out_size)
{
    const float* ev     = (const float*)d_in[0];
    const float* teach  = (const float*)d_in[1];
    const float* w_init = (const float*)d_in[2];
    const float* b_init = (const float*)d_in[3];
    const float* w_ih   = (const float*)d_in[4];
    const float* w_hh   = (const float*)d_in[5];
    const float* b_ih   = (const float*)d_in[6];
    const float* b_hh   = (const float*)d_in[7];
    const float* w_out  = (const float*)d_in[8];
    const float* b_out  = (const float*)d_in[9];
    float* out = (float*)d_out;

    float* hbase;
    __nv_bfloat16 *hhib, *hlob, *whi, *wlo;
    cudaGetSymbolAddress((void**)&hbase, g_h);
    cudaGetSymbolAddress((void**)&hhib, g_hhi);
    cudaGetSymbolAddress((void**)&hlob, g_hlo);
    cudaGetSymbolAddress((void**)&whi, g_whi);
    cudaGetSymbolAddress((void**)&wlo, g_wlo);

    float* hbuf[2] = { hbase, hbase + (size_t)BB * HH };
    __nv_bfloat16* hhi[2] = { hhib, hhib + (size_t)BB * HH };
    __nv_bfloat16* hlo[2] = { hlob, hlob + (size_t)BB * HH };

    cudaFuncSetAttribute(gru_step_kernel,
                         cudaFuncAttributeMaxDynamicSharedMemorySize, SMEM_BYTES);

    // split weights (deterministic every call)
    split_kernel<<<(3 * HH * HH + 255) / 256, 256>>>(w_hh, whi, wlo, 3 * HH * HH);

    // h0 = tanh(ev @ w_init^T + b_init), then split
    gemm_h0_kernel<<<dim3(HH / 128, BB / 128), 256>>>(ev, w_init, hbuf[0], BB, HH, DD, b_init);
    split_kernel<<<(BB * HH + 255) / 256, 256>>>(hbuf[0], hhi[0], hlo[0], BB * HH);

    init_deltas_kernel<<<(BB * TT * 2 + 255) / 256, 256>>>(out, b_out);

    for (int t = 0; t < TT; t++) {
        int cur = t & 1, nxt = cur ^ 1;
        gru_step_kernel<<<dim3(16, 32), 384, SMEM_BYTES>>>(
            hbuf[cur], hhi[cur], hlo[cur],
            hbuf[nxt], hhi[nxt], hlo[nxt],
            whi, wlo, teach, t, b_hh, w_ih, b_ih, w_out, out);
    }

    cumsum_kernel<<<(BB * 2 + 255) / 256, 256>>>(out, out + (size_t)BB * TT * 2);
}

// round 5
// speedup vs baseline: 2.1777x; 1.0223x over previous
#include <cuda_runtime.h>
#include <cuda_bf16.h>
#include <stdint.h>

// ---------------------------------------------------------------------------
// Problem constants
// ---------------------------------------------------------------------------
constexpr int BB = 4096;   // batch
constexpr int DD = 1024;   // ev_context dim
constexpr int HH = 1024;   // hidden
constexpr int TT = 50;     // timesteps

// ---------------------------------------------------------------------------
// Device scratch (no allocs): ping-pong h (fp32 + bf16 hi/lo), split weights
// ---------------------------------------------------------------------------
__device__ float         g_h  [2][(size_t)BB * HH];
__device__ __nv_bfloat16 g_hhi[2][(size_t)BB * HH];
__device__ __nv_bfloat16 g_hlo[2][(size_t)BB * HH];
__device__ __nv_bfloat16 g_whi[(size_t)3 * HH * HH];
__device__ __nv_bfloat16 g_wlo[(size_t)3 * HH * HH];

__device__ __forceinline__ float sigmoidf_(float x) {
    return 1.0f / (1.0f + __expf(-x));
}
__device__ __forceinline__ float tanh_fast(float x) {
    return 2.0f / (1.0f + __expf(-2.0f * x)) - 1.0f;
}

// ---------------------------------------------------------------------------
// PTX helpers: portable sm_80+ instructions only (compute_103-safe).
// ---------------------------------------------------------------------------
__device__ __forceinline__ uint32_t smem_u32(const void* p) {
    uint32_t a;
    asm("{ .reg .u64 t; cvta.to.shared.u64 t, %1; cvt.u32.u64 %0, t; }"
        : "=r"(a) : "l"(p));
    return a;
}
__device__ __forceinline__ uint32_t swz(uint32_t o) {   // SW128: 16B-granular XOR
    return o ^ ((o >> 3) & 0x70);
}
__device__ __forceinline__ void cp_async16(uint32_t dst, const void* src) {
    asm volatile("cp.async.cg.shared.global [%0], [%1], 16;"
                 :: "r"(dst), "l"(src) : "memory");
}
__device__ __forceinline__ void cp_commit() {
    asm volatile("cp.async.commit_group;" ::: "memory");
}
__device__ __forceinline__ void cp_wait2() {
    asm volatile("cp.async.wait_group 2;" ::: "memory");
}
__device__ __forceinline__ void ldsm4(uint32_t* r, uint32_t a) {
    asm volatile("ldmatrix.sync.aligned.m8n8.x4.shared.b16 {%0,%1,%2,%3}, [%4];"
                 : "=r"(r[0]), "=r"(r[1]), "=r"(r[2]), "=r"(r[3]) : "r"(a));
}
__device__ __forceinline__ void mma16816(float* d, const uint32_t* a, const uint32_t* b) {
    asm volatile(
        "mma.sync.aligned.m16n8k16.row.col.f32.bf16.bf16.f32 "
        "{%0,%1,%2,%3}, {%4,%5,%6,%7}, {%8,%9}, {%0,%1,%2,%3};"
        : "+f"(d[0]), "+f"(d[1]), "+f"(d[2]), "+f"(d[3])
        : "r"(a[0]), "r"(a[1]), "r"(a[2]), "r"(a[3]), "r"(b[0]), "r"(b[1]));
}

// Stage: A tile 128x64 bf16 (16KB) + B tile 192x64 bf16 (24KB), 4 stages
constexpr int STAGE   = 40960;
constexpr int OFF_B   = 16384;
constexpr int NSTAGE  = 4;
constexpr int NCHUNK  = 48;                  // 3 segments x 16 chunks of K=64
constexpr int PITCH   = 196;                 // epilogue gh smem pitch (floats)
constexpr int SMEM_BYTES = NSTAGE * STAGE;   // 163840 (> 128*PITCH*4 = 100352)

// issue cp.async loads for chunk c into stage s
__device__ __forceinline__ void load_chunk(
    int c, int s, int tid, int bm, int bu, uint32_t sbase,
    const __nv_bfloat16* hhi, const __nv_bfloat16* hlo,
    const __nv_bfloat16* whi, const __nv_bfloat16* wlo)
{
    const int seg = c >> 4;
    const int kk = (c & 15) * 64;
    const __nv_bfloat16* sa = (seg < 2) ? hhi : hlo;
    const __nv_bfloat16* sb = (seg == 1) ? wlo : whi;
    const uint32_t stA = sbase + s * STAGE;
    const uint32_t stB = stA + OFF_B;

    // A: 128 rows x 64 k -> 1024 x 16B
#pragma unroll
    for (int i = 0; i < 3; i++) {
        int v = tid + i * 384;
        if (v < 1024) {
            int r = v >> 3, kv = v & 7;
            cp_async16(stA + swz(r * 128 + kv * 16),
                       sa + (size_t)(bm * 128 + r) * 1024 + kk + kv * 8);
        }
    }
    // B: 192 rows (3 gates x 64 units) x 64 k -> 1536 x 16B
#pragma unroll
    for (int i = 0; i < 4; i++) {
        int v = tid + i * 384;
        int j = v >> 3, kv = v & 7;
        int g = j >> 6, u = j & 63;
        cp_async16(stB + swz(j * 128 + kv * 16),
                   sb + (size_t)(g * 1024 + bu * 64 + u) * 1024 + kk + kv * 8);
    }
}

// ---------------------------------------------------------------------------
// Fused recurrent step (HMMA): tile 128 batch x (3 gates x 64 units)
// grid (16, 32), 384 threads, dyn smem SMEM_BYTES, 4-stage pipeline
// ---------------------------------------------------------------------------
__global__ __launch_bounds__(384, 1) void gru_step_kernel(
    const float* __restrict__ hprev,
    const __nv_bfloat16* __restrict__ hhi, const __nv_bfloat16* __restrict__ hlo,
    float* __restrict__ hout,
    __nv_bfloat16* __restrict__ hhio, __nv_bfloat16* __restrict__ hloo,
    const __nv_bfloat16* __restrict__ whi, const __nv_bfloat16* __restrict__ wlo,
    const float* __restrict__ teacher, int t,
    const float* __restrict__ b_hh, const float* __restrict__ w_ih,
    const float* __restrict__ b_ih, const float* __restrict__ w_out,
    float* __restrict__ deltas)
{
    extern __shared__ __align__(1024) char smem[];
    const uint32_t sbase = smem_u32(smem);
    const int tid = threadIdx.x;
    const int lane = tid & 31, wid = tid >> 5;
    const int bu = blockIdx.x, bm = blockIdx.y;
    const int wm = wid & 3, wg = wid >> 2;   // warp grid 4(m) x 3(gate)
    const int m0 = wm * 32;

    float acc[2][8][4];
#pragma unroll
    for (int a = 0; a < 2; a++)
#pragma unroll
        for (int b = 0; b < 8; b++)
#pragma unroll
            for (int q = 0; q < 4; q++) acc[a][b][q] = 0.0f;

    // prologue: stages 0..2 in flight
#pragma unroll
    for (int p = 0; p < NSTAGE - 1; p++) {
        load_chunk(p, p, tid, bm, bu, sbase, hhi, hlo, whi, wlo);
        cp_commit();
    }

    for (int c = 0; c < NCHUNK; c++) {
        cp_wait2();          // stage c%4 resident (<=2 groups still pending)
        __syncthreads();     // data visible; all warps done reading stage (c-1)%4

        // prefetch chunk c+3 into buffer (c+3)%4 == (c-1)%4
        if (c + NSTAGE - 1 < NCHUNK)
            load_chunk(c + NSTAGE - 1, (c + NSTAGE - 1) & (NSTAGE - 1),
                       tid, bm, bu, sbase, hhi, hlo, whi, wlo);
        cp_commit();         // empty group near the tail keeps counts aligned

        const uint32_t stA = sbase + (c & (NSTAGE - 1)) * STAGE;
        const uint32_t stB = stA + OFF_B;
#pragma unroll
        for (int ks = 0; ks < 4; ks++) {
            uint32_t af[2][4];
#pragma unroll
            for (int mt = 0; mt < 2; mt++) {
                int r = m0 + mt * 16 + (lane & 15);
                int kb = ks * 32 + ((lane >> 4) << 4);
                ldsm4(af[mt], stA + swz(r * 128 + kb));
            }
            uint32_t bf[4][4];
#pragma unroll
            for (int p = 0; p < 4; p++) {
                int r = wg * 64 + p * 16 + (lane & 7) + ((lane & 16) ? 8 : 0);
                int kb = ks * 32 + ((lane & 8) ? 16 : 0);
                ldsm4(bf[p], stB + swz(r * 128 + kb));
            }
#pragma unroll
            for (int mt = 0; mt < 2; mt++)
#pragma unroll
                for (int p = 0; p < 4; p++) {
                    mma16816(acc[mt][2 * p],     af[mt], &bf[p][0]);
                    mma16816(acc[mt][2 * p + 1], af[mt], &bf[p][2]);
                }
        }
    }
    __syncthreads();  // all compute done before epilogue overlays stage smem

    // ------ epilogue: accs -> smem gh tile -----------------------------------
    float* ghs = (float*)smem;
#pragma unroll
    for (int mt = 0; mt < 2; mt++)
#pragma unroll
        for (int nf = 0; nf < 8; nf++) {
            int row = m0 + mt * 16 + (lane >> 2);
            int col = wg * 64 + nf * 8 + 2 * (lane & 3);
            *(float2*)&ghs[row * PITCH + col] =
                make_float2(acc[mt][nf][0], acc[mt][nf][1]);
            *(float2*)&ghs[(row + 8) * PITCH + col] =
                make_float2(acc[mt][nf][2], acc[mt][nf][3]);
        }
    __syncthreads();

    // ------ GRU cell + delta partials: warps 0-7, lane = unit offset ---------
    if (tid < 256) {
        const int u = tid & 63;
        const int r0 = tid >> 6;
        const int col = bu * 64 + u;

        const float bhr = b_hh[col], bhz = b_hh[HH + col], bhn = b_hh[2 * HH + col];
        const float wr0 = w_ih[2 * col],            wr1 = w_ih[2 * col + 1];
        const float wz0 = w_ih[2 * (HH + col)],     wz1 = w_ih[2 * (HH + col) + 1];
        const float wn0 = w_ih[2 * (2 * HH + col)], wn1 = w_ih[2 * (2 * HH + col) + 1];
        const float bir = b_ih[col], biz = b_ih[HH + col], bin_ = b_ih[2 * HH + col];
        const float wo0 = w_out[col], wo1 = w_out[HH + col];

        for (int k = 0; k < 32; k++) {
            const int r = r0 * 32 + k;
            const int rg = bm * 128 + r;
            float p0 = 0.0f, p1 = 0.0f;
            if (t > 0) {
                size_t to = ((size_t)rg * TT + (t - 1)) * 2;
                p0 = teacher[to]; p1 = teacher[to + 1];
            }
            float hr = ghs[r * PITCH + u]        + bhr;
            float hz = ghs[r * PITCH + 64 + u]   + bhz;
            float hn = ghs[r * PITCH + 128 + u]  + bhn;
            float rr = sigmoidf_(wr0 * p0 + wr1 * p1 + bir + hr);
            float zz = sigmoidf_(wz0 * p0 + wz1 * p1 + biz + hz);
            float nn = tanh_fast(wn0 * p0 + wn1 * p1 + bin_ + rr * hn);
            size_t go = (size_t)rg * HH + col;
            float h = hprev[go];
            float hv = (1.0f - zz) * nn + zz * h;

            hout[go] = hv;
            __nv_bfloat16 hb = __float2bfloat16(hv);
            hhio[go] = hb;
            hloo[go] = __float2bfloat16(hv - __bfloat162float(hb));

            float s0 = hv * wo0, s1 = hv * wo1;
#pragma unroll
            for (int o = 16; o > 0; o >>= 1) {
                s0 += __shfl_xor_sync(0xFFFFFFFFu, s0, o);
                s1 += __shfl_xor_sync(0xFFFFFFFFu, s1, o);
            }
            if (lane == 0) {
                atomicAdd(&deltas[((size_t)rg * TT + t) * 2],     s0);
                atomicAdd(&deltas[((size_t)rg * TT + t) * 2 + 1], s1);
            }
        }
    }
}

// ---------------------------------------------------------------------------
// fp32 SGEMM for h0 = tanh(ev @ w_init^T + b_init)  (one-time)
// ---------------------------------------------------------------------------
__global__ __launch_bounds__(256, 2) void gemm_h0_kernel(
    const float* __restrict__ A, const float* __restrict__ Bm,
    float* __restrict__ C, int M, int N, int K, const float* __restrict__ bias)
{
    __shared__ __align__(16) float As[8][128];
    __shared__ __align__(16) float Bs[8][128];
    const int tid = threadIdx.x;
    const int bm = blockIdx.y, bn = blockIdx.x;
    const float* Ablk = A + (size_t)bm * 128 * K;
    const float* Bblk = Bm + (size_t)bn * 128 * K;
    const int lr = tid >> 1, lc = (tid & 1) * 4;
    const int tx = tid & 15, ty = tid >> 4;
    float acc[8][8];
#pragma unroll
    for (int i = 0; i < 8; i++)
#pragma unroll
        for (int j = 0; j < 8; j++) acc[i][j] = 0.0f;
    for (int k0 = 0; k0 < K; k0 += 8) {
        float4 a4 = *(const float4*)(Ablk + (size_t)lr * K + k0 + lc);
        float4 b4 = *(const float4*)(Bblk + (size_t)lr * K + k0 + lc);
        As[lc + 0][lr] = a4.x; As[lc + 1][lr] = a4.y;
        As[lc + 2][lr] = a4.z; As[lc + 3][lr] = a4.w;
        Bs[lc + 0][lr] = b4.x; Bs[lc + 1][lr] = b4.y;
        Bs[lc + 2][lr] = b4.z; Bs[lc + 3][lr] = b4.w;
        __syncthreads();
#pragma unroll
        for (int k = 0; k < 8; k++) {
            float ra[8], rb[8];
            *(float4*)(ra)     = *(const float4*)&As[k][ty * 8];
            *(float4*)(ra + 4) = *(const float4*)&As[k][ty * 8 + 4];
            *(float4*)(rb)     = *(const float4*)&Bs[k][tx * 8];
            *(float4*)(rb + 4) = *(const float4*)&Bs[k][tx * 8 + 4];
#pragma unroll
            for (int i = 0; i < 8; i++)
#pragma unroll
                for (int j = 0; j < 8; j++) acc[i][j] += ra[i] * rb[j];
        }
        __syncthreads();
    }
    const int row0 = bm * 128 + ty * 8, col0 = bn * 128 + tx * 8;
#pragma unroll
    for (int i = 0; i < 8; i++) {
        float* crow = C + (size_t)(row0 + i) * N + col0;
#pragma unroll
        for (int j = 0; j < 8; j++)
            crow[j] = tanh_fast(acc[i][j] + bias[col0 + j]);
    }
}

// split fp32 -> bf16 hi + lo residual
__global__ void split_kernel(const float* __restrict__ src,
                             __nv_bfloat16* __restrict__ hi,
                             __nv_bfloat16* __restrict__ lo, int n)
{
    int i = blockIdx.x * 256 + threadIdx.x;
    if (i < n) {
        float v = src[i];
        __nv_bfloat16 h = __float2bfloat16(v);
        hi[i] = h;
        lo[i] = __float2bfloat16(v - __bfloat162float(h));
    }
}

// deltas[b,t,c] = b_out[c]  (atomicAdd partials land on top)
__global__ void init_deltas_kernel(float* __restrict__ deltas, const float* __restrict__ b_out)
{
    int i = blockIdx.x * 256 + threadIdx.x;
    if (i < BB * TT * 2) deltas[i] = b_out[i & 1];
}

__global__ void cumsum_kernel(const float* __restrict__ deltas, float* __restrict__ pos)
{
    int idx = blockIdx.x * blockDim.x + threadIdx.x;
    if (idx >= BB * 2) return;
    int b = idx >> 1, c = idx & 1;
    float acc = 0.0f;
    for (int t = 0; t < TT; t++) {
        size_t o = ((size_t)b * TT + t) * 2 + c;
        acc += deltas[o];
        pos[o] = acc;
    }
}

// ---------------------------------------------------------------------------
// kernel_launch (graph-capturable, allocation-free)
// ---------------------------------------------------------------------------
extern "C" void kernel_launch(void* const* d_in, const int* in_sizes, int n_in,
                              void* d_out, int out_size)
{
    const float* ev     = (const float*)d_in[0];
    const float* teach  = (const float*)d_in[1];
    const float* w_init = (const float*)d_in[2];
    const float* b_init = (const float*)d_in[3];
    const float* w_ih   = (const float*)d_in[4];
    const float* w_hh   = (const float*)d_in[5];
    const float* b_ih   = (const float*)d_in[6];
    const float* b_hh   = (const float*)d_in[7];
    const float* w_out  = (const float*)d_in[8];
    const float* b_out  = (const float*)d_in[9];
    float* out = (float*)d_out;

    float* hbase;
    __nv_bfloat16 *hhib, *hlob, *whi, *wlo;
    cudaGetSymbolAddress((void**)&hbase, g_h);
    cudaGetSymbolAddress((void**)&hhib, g_hhi);
    cudaGetSymbolAddress((void**)&hlob, g_hlo);
    cudaGetSymbolAddress((void**)&whi, g_whi);
    cudaGetSymbolAddress((void**)&wlo, g_wlo);

    float* hbuf[2] = { hbase, hbase + (size_t)BB * HH };
    __nv_bfloat16* hhi[2] = { hhib, hhib + (size_t)BB * HH };
    __nv_bfloat16* hlo[2] = { hlob, hlob + (size_t)BB * HH };

    cudaFuncSetAttribute(gru_step_kernel,
                         cudaFuncAttributeMaxDynamicSharedMemorySize, SMEM_BYTES);

    // split weights (deterministic every call)
    split_kernel<<<(3 * HH * HH + 255) / 256, 256>>>(w_hh, whi, wlo, 3 * HH * HH);

    // h0 = tanh(ev @ w_init^T + b_init), then split
    gemm_h0_kernel<<<dim3(HH / 128, BB / 128), 256>>>(ev, w_init, hbuf[0], BB, HH, DD, b_init);
    split_kernel<<<(BB * HH + 255) / 256, 256>>>(hbuf[0], hhi[0], hlo[0], BB * HH);

    init_deltas_kernel<<<(BB * TT * 2 + 255) / 256, 256>>>(out, b_out);

    for (int t = 0; t < TT; t++) {
        int cur = t & 1, nxt = cur ^ 1;
        gru_step_kernel<<<dim3(16, 32), 384, SMEM_BYTES>>>(
            hbuf[cur], hhi[cur], hlo[cur],
            hbuf[nxt], hhi[nxt], hlo[nxt],
            whi, wlo, teach, t, b_hh, w_ih, b_ih, w_out, out);
    }

    cumsum_kernel<<<(BB * 2 + 255) / 256, 256>>>(out, out + (size_t)BB * TT * 2);
}

// round 6
// speedup vs baseline: 4.4308x; 2.0346x over previous
#include <cuda_runtime.h>
#include <cuda_fp16.h>
#include <stdint.h>

// ---------------------------------------------------------------------------
// Problem constants
// ---------------------------------------------------------------------------
constexpr int BB = 4096;   // batch
constexpr int DD = 1024;   // ev_context dim
constexpr int HH = 1024;   // hidden
constexpr int TT = 50;     // timesteps

// ---------------------------------------------------------------------------
// Device scratch (no allocs): ping-pong h (fp32 + fp16 copy), fp16 weights
// ---------------------------------------------------------------------------
__device__ float  g_h [2][(size_t)BB * HH];
__device__ __half g_hf[2][(size_t)BB * HH];
__device__ __half g_wf[(size_t)3 * HH * HH];

__device__ __forceinline__ float sigmoidf_(float x) {
    return 1.0f / (1.0f + __expf(-x));
}
__device__ __forceinline__ float tanh_fast(float x) {
    return 2.0f / (1.0f + __expf(-2.0f * x)) - 1.0f;
}

// ---------------------------------------------------------------------------
// PTX helpers: portable sm_80+ instructions only (compute_103-safe).
// ---------------------------------------------------------------------------
__device__ __forceinline__ uint32_t smem_u32(const void* p) {
    uint32_t a;
    asm("{ .reg .u64 t; cvta.to.shared.u64 t, %1; cvt.u32.u64 %0, t; }"
        : "=r"(a) : "l"(p));
    return a;
}
__device__ __forceinline__ uint32_t swz(uint32_t o) {   // SW128: 16B-granular XOR
    return o ^ ((o >> 3) & 0x70);
}
__device__ __forceinline__ void cp_async16(uint32_t dst, const void* src) {
    asm volatile("cp.async.cg.shared.global [%0], [%1], 16;"
                 :: "r"(dst), "l"(src) : "memory");
}
__device__ __forceinline__ void cp_commit() {
    asm volatile("cp.async.commit_group;" ::: "memory");
}
__device__ __forceinline__ void cp_wait2() {
    asm volatile("cp.async.wait_group 2;" ::: "memory");
}
__device__ __forceinline__ void ldsm4(uint32_t* r, uint32_t a) {
    asm volatile("ldmatrix.sync.aligned.m8n8.x4.shared.b16 {%0,%1,%2,%3}, [%4];"
                 : "=r"(r[0]), "=r"(r[1]), "=r"(r[2]), "=r"(r[3]) : "r"(a));
}
__device__ __forceinline__ void mma16816(float* d, const uint32_t* a, const uint32_t* b) {
    asm volatile(
        "mma.sync.aligned.m16n8k16.row.col.f32.f16.f16.f32 "
        "{%0,%1,%2,%3}, {%4,%5,%6,%7}, {%8,%9}, {%0,%1,%2,%3};"
        : "+f"(d[0]), "+f"(d[1]), "+f"(d[2]), "+f"(d[3])
        : "r"(a[0]), "r"(a[1]), "r"(a[2]), "r"(a[3]), "r"(b[0]), "r"(b[1]));
}

// Stage: A tile 128x64 fp16 (16KB) + B tile 192x64 fp16 (24KB), 4 stages
constexpr int STAGE   = 40960;
constexpr int OFF_B   = 16384;
constexpr int NSTAGE  = 4;
constexpr int NCHUNK  = 16;                  // K=1024 in chunks of 64 (single term)
constexpr int PITCH   = 196;                 // epilogue gh smem pitch (floats)
constexpr int SMEM_BYTES = NSTAGE * STAGE;   // 163840 (> 128*PITCH*4 = 100352)

// issue cp.async loads for chunk c into stage s
__device__ __forceinline__ void load_chunk(
    int c, int s, int tid, int bm, int bu, uint32_t sbase,
    const __half* hf, const __half* wf)
{
    const int kk = c * 64;
    const uint32_t stA = sbase + s * STAGE;
    const uint32_t stB = stA + OFF_B;

    // A: 128 rows x 64 k -> 1024 x 16B
#pragma unroll
    for (int i = 0; i < 3; i++) {
        int v = tid + i * 384;
        if (v < 1024) {
            int r = v >> 3, kv = v & 7;
            cp_async16(stA + swz(r * 128 + kv * 16),
                       hf + (size_t)(bm * 128 + r) * 1024 + kk + kv * 8);
        }
    }
    // B: 192 rows (3 gates x 64 units) x 64 k -> 1536 x 16B
#pragma unroll
    for (int i = 0; i < 4; i++) {
        int v = tid + i * 384;
        int j = v >> 3, kv = v & 7;
        int g = j >> 6, u = j & 63;
        cp_async16(stB + swz(j * 128 + kv * 16),
                   wf + (size_t)(g * 1024 + bu * 64 + u) * 1024 + kk + kv * 8);
    }
}

// ---------------------------------------------------------------------------
// Fused recurrent step (HMMA fp16): tile 128 batch x (3 gates x 64 units)
// grid (16, 32), 384 threads, dyn smem SMEM_BYTES, 4-stage pipeline
// ---------------------------------------------------------------------------
__global__ __launch_bounds__(384, 1) void gru_step_kernel(
    const float* __restrict__ hprev,
    const __half* __restrict__ hf,
    float* __restrict__ hout,
    __half* __restrict__ hfo,
    const __half* __restrict__ wf,
    const float* __restrict__ teacher, int t,
    const float* __restrict__ b_hh, const float* __restrict__ w_ih,
    const float* __restrict__ b_ih, const float* __restrict__ w_out,
    float* __restrict__ deltas)
{
    extern __shared__ __align__(1024) char smem[];
    const uint32_t sbase = smem_u32(smem);
    const int tid = threadIdx.x;
    const int lane = tid & 31, wid = tid >> 5;
    const int bu = blockIdx.x, bm = blockIdx.y;
    const int wm = wid & 3, wg = wid >> 2;   // warp grid 4(m) x 3(gate)
    const int m0 = wm * 32;

    float acc[2][8][4];
#pragma unroll
    for (int a = 0; a < 2; a++)
#pragma unroll
        for (int b = 0; b < 8; b++)
#pragma unroll
            for (int q = 0; q < 4; q++) acc[a][b][q] = 0.0f;

    // prologue: stages 0..2 in flight
#pragma unroll
    for (int p = 0; p < NSTAGE - 1; p++) {
        load_chunk(p, p, tid, bm, bu, sbase, hf, wf);
        cp_commit();
    }

    for (int c = 0; c < NCHUNK; c++) {
        cp_wait2();          // stage c%4 resident (<=2 groups still pending)
        __syncthreads();     // data visible; all warps done reading stage (c-1)%4

        if (c + NSTAGE - 1 < NCHUNK)
            load_chunk(c + NSTAGE - 1, (c + NSTAGE - 1) & (NSTAGE - 1),
                       tid, bm, bu, sbase, hf, wf);
        cp_commit();         // empty group near the tail keeps counts aligned

        const uint32_t stA = sbase + (c & (NSTAGE - 1)) * STAGE;
        const uint32_t stB = stA + OFF_B;
#pragma unroll
        for (int ks = 0; ks < 4; ks++) {
            uint32_t af[2][4];
#pragma unroll
            for (int mt = 0; mt < 2; mt++) {
                int r = m0 + mt * 16 + (lane & 15);
                int kb = ks * 32 + ((lane >> 4) << 4);
                ldsm4(af[mt], stA + swz(r * 128 + kb));
            }
            uint32_t bf[4][4];
#pragma unroll
            for (int p = 0; p < 4; p++) {
                int r = wg * 64 + p * 16 + (lane & 7) + ((lane & 16) ? 8 : 0);
                int kb = ks * 32 + ((lane & 8) ? 16 : 0);
                ldsm4(bf[p], stB + swz(r * 128 + kb));
            }
#pragma unroll
            for (int mt = 0; mt < 2; mt++)
#pragma unroll
                for (int p = 0; p < 4; p++) {
                    mma16816(acc[mt][2 * p],     af[mt], &bf[p][0]);
                    mma16816(acc[mt][2 * p + 1], af[mt], &bf[p][2]);
                }
        }
    }
    __syncthreads();  // all compute done before epilogue overlays stage smem

    // ------ epilogue: accs -> smem gh tile -----------------------------------
    float* ghs = (float*)smem;
#pragma unroll
    for (int mt = 0; mt < 2; mt++)
#pragma unroll
        for (int nf = 0; nf < 8; nf++) {
            int row = m0 + mt * 16 + (lane >> 2);
            int col = wg * 64 + nf * 8 + 2 * (lane & 3);
            *(float2*)&ghs[row * PITCH + col] =
                make_float2(acc[mt][nf][0], acc[mt][nf][1]);
            *(float2*)&ghs[(row + 8) * PITCH + col] =
                make_float2(acc[mt][nf][2], acc[mt][nf][3]);
        }
    __syncthreads();

    // ------ GRU cell + delta partials: warps 0-7, lane = unit offset ---------
    if (tid < 256) {
        const int u = tid & 63;
        const int r0 = tid >> 6;
        const int col = bu * 64 + u;

        const float bhr = b_hh[col], bhz = b_hh[HH + col], bhn = b_hh[2 * HH + col];
        const float wr0 = w_ih[2 * col],            wr1 = w_ih[2 * col + 1];
        const float wz0 = w_ih[2 * (HH + col)],     wz1 = w_ih[2 * (HH + col) + 1];
        const float wn0 = w_ih[2 * (2 * HH + col)], wn1 = w_ih[2 * (2 * HH + col) + 1];
        const float bir = b_ih[col], biz = b_ih[HH + col], bin_ = b_ih[2 * HH + col];
        const float wo0 = w_out[col], wo1 = w_out[HH + col];

        for (int k = 0; k < 32; k++) {
            const int r = r0 * 32 + k;
            const int rg = bm * 128 + r;
            float p0 = 0.0f, p1 = 0.0f;
            if (t > 0) {
                size_t to = ((size_t)rg * TT + (t - 1)) * 2;
                p0 = teacher[to]; p1 = teacher[to + 1];
            }
            float hr = ghs[r * PITCH + u]        + bhr;
            float hz = ghs[r * PITCH + 64 + u]   + bhz;
            float hn = ghs[r * PITCH + 128 + u]  + bhn;
            float rr = sigmoidf_(wr0 * p0 + wr1 * p1 + bir + hr);
            float zz = sigmoidf_(wz0 * p0 + wz1 * p1 + biz + hz);
            float nn = tanh_fast(wn0 * p0 + wn1 * p1 + bin_ + rr * hn);
            size_t go = (size_t)rg * HH + col;
            float h = hprev[go];
            float hv = (1.0f - zz) * nn + zz * h;

            hout[go] = hv;
            hfo[go]  = __float2half(hv);

            float s0 = hv * wo0, s1 = hv * wo1;
#pragma unroll
            for (int o = 16; o > 0; o >>= 1) {
                s0 += __shfl_xor_sync(0xFFFFFFFFu, s0, o);
                s1 += __shfl_xor_sync(0xFFFFFFFFu, s1, o);
            }
            if (lane == 0) {
                atomicAdd(&deltas[((size_t)rg * TT + t) * 2],     s0);
                atomicAdd(&deltas[((size_t)rg * TT + t) * 2 + 1], s1);
            }
        }
    }
}

// ---------------------------------------------------------------------------
// fp32 SGEMM for h0 = tanh(ev @ w_init^T + b_init)  (one-time)
// ---------------------------------------------------------------------------
__global__ __launch_bounds__(256, 2) void gemm_h0_kernel(
    const float* __restrict__ A, const float* __restrict__ Bm,
    float* __restrict__ C, int M, int N, int K, const float* __restrict__ bias)
{
    __shared__ __align__(16) float As[8][128];
    __shared__ __align__(16) float Bs[8][128];
    const int tid = threadIdx.x;
    const int bm = blockIdx.y, bn = blockIdx.x;
    const float* Ablk = A + (size_t)bm * 128 * K;
    const float* Bblk = Bm + (size_t)bn * 128 * K;
    const int lr = tid >> 1, lc = (tid & 1) * 4;
    const int tx = tid & 15, ty = tid >> 4;
    float acc[8][8];
#pragma unroll
    for (int i = 0; i < 8; i++)
#pragma unroll
        for (int j = 0; j < 8; j++) acc[i][j] = 0.0f;
    for (int k0 = 0; k0 < K; k0 += 8) {
        float4 a4 = *(const float4*)(Ablk + (size_t)lr * K + k0 + lc);
        float4 b4 = *(const float4*)(Bblk + (size_t)lr * K + k0 + lc);
        As[lc + 0][lr] = a4.x; As[lc + 1][lr] = a4.y;
        As[lc + 2][lr] = a4.z; As[lc + 3][lr] = a4.w;
        Bs[lc + 0][lr] = b4.x; Bs[lc + 1][lr] = b4.y;
        Bs[lc + 2][lr] = b4.z; Bs[lc + 3][lr] = b4.w;
        __syncthreads();
#pragma unroll
        for (int k = 0; k < 8; k++) {
            float ra[8], rb[8];
            *(float4*)(ra)     = *(const float4*)&As[k][ty * 8];
            *(float4*)(ra + 4) = *(const float4*)&As[k][ty * 8 + 4];
            *(float4*)(rb)     = *(const float4*)&Bs[k][tx * 8];
            *(float4*)(rb + 4) = *(const float4*)&Bs[k][tx * 8 + 4];
#pragma unroll
            for (int i = 0; i < 8; i++)
#pragma unroll
                for (int j = 0; j < 8; j++) acc[i][j] += ra[i] * rb[j];
        }
        __syncthreads();
    }
    const int row0 = bm * 128 + ty * 8, col0 = bn * 128 + tx * 8;
#pragma unroll
    for (int i = 0; i < 8; i++) {
        float* crow = C + (size_t)(row0 + i) * N + col0;
#pragma unroll
        for (int j = 0; j < 8; j++)
            crow[j] = tanh_fast(acc[i][j] + bias[col0 + j]);
    }
}

// fp32 -> fp16 convert
__global__ void convert_kernel(const float* __restrict__ src,
                               __half* __restrict__ dst, int n)
{
    int i = blockIdx.x * 256 + threadIdx.x;
    if (i < n) dst[i] = __float2half(src[i]);
}

// deltas[b,t,c] = b_out[c]  (atomicAdd partials land on top)
__global__ void init_deltas_kernel(float* __restrict__ deltas, const float* __restrict__ b_out)
{
    int i = blockIdx.x * 256 + threadIdx.x;
    if (i < BB * TT * 2) deltas[i] = b_out[i & 1];
}

__global__ void cumsum_kernel(const float* __restrict__ deltas, float* __restrict__ pos)
{
    int idx = blockIdx.x * blockDim.x + threadIdx.x;
    if (idx >= BB * 2) return;
    int b = idx >> 1, c = idx & 1;
    float acc = 0.0f;
    for (int t = 0; t < TT; t++) {
        size_t o = ((size_t)b * TT + t) * 2 + c;
        acc += deltas[o];
        pos[o] = acc;
    }
}

// ---------------------------------------------------------------------------
// kernel_launch (graph-capturable, allocation-free)
// ---------------------------------------------------------------------------
extern "C" void kernel_launch(void* const* d_in, const int* in_sizes, int n_in,
                              void* d_out, int out_size)
{
    const float* ev     = (const float*)d_in[0];
    const float* teach  = (const float*)d_in[1];
    const float* w_init = (const float*)d_in[2];
    const float* b_init = (const float*)d_in[3];
    const float* w_ih   = (const float*)d_in[4];
    const float* w_hh   = (const float*)d_in[5];
    const float* b_ih   = (const float*)d_in[6];
    const float* b_hh   = (const float*)d_in[7];
    const float* w_out  = (const float*)d_in[8];
    const float* b_out  = (const float*)d_in[9];
    float* out = (float*)d_out;

    float* hbase;
    __half *hfb, *wfb;
    cudaGetSymbolAddress((void**)&hbase, g_h);
    cudaGetSymbolAddress((void**)&hfb, g_hf);
    cudaGetSymbolAddress((void**)&wfb, g_wf);

    float* hbuf[2] = { hbase, hbase + (size_t)BB * HH };
    __half* hf[2] = { hfb, hfb + (size_t)BB * HH };

    cudaFuncSetAttribute(gru_step_kernel,
                         cudaFuncAttributeMaxDynamicSharedMemorySize, SMEM_BYTES);

    // w_hh -> fp16 (deterministic every call)
    convert_kernel<<<(3 * HH * HH + 255) / 256, 256>>>(w_hh, wfb, 3 * HH * HH);

    // h0 = tanh(ev @ w_init^T + b_init), then fp16 copy
    gemm_h0_kernel<<<dim3(HH / 128, BB / 128), 256>>>(ev, w_init, hbuf[0], BB, HH, DD, b_init);
    convert_kernel<<<(BB * HH + 255) / 256, 256>>>(hbuf[0], hf[0], BB * HH);

    init_deltas_kernel<<<(BB * TT * 2 + 255) / 256, 256>>>(out, b_out);

    for (int t = 0; t < TT; t++) {
        int cur = t & 1, nxt = cur ^ 1;
        gru_step_kernel<<<dim3(16, 32), 384, SMEM_BYTES>>>(
            hbuf[cur], hf[cur], hbuf[nxt], hf[nxt],
            wfb, teach, t, b_hh, w_ih, b_ih, w_out, out);
    }

    cumsum_kernel<<<(BB * 2 + 255) / 256, 256>>>(out, out + (size_t)BB * TT * 2);
}